// round 4
// baseline (speedup 1.0000x reference)
#include <cuda_runtime.h>
#include <math.h>

// Problem constants
#define BATCH 8
#define SEQ   2048
#define EMB   1024
#define HD    128
#define MROWS (BATCH*SEQ)   // 16384

// Scratch for projected q,k,v (fp32, accurate)
__device__ float g_q[MROWS*HD];
__device__ float g_k[MROWS*HD];
__device__ float g_v[MROWS*HD];

// ---------------------------------------------------------------------------
// Helpers: tf32 rounding + mma.sync tf32
// ---------------------------------------------------------------------------
__device__ __forceinline__ float tf32r(float x) {
    unsigned u;
    asm("cvt.rna.tf32.f32 %0, %1;" : "=r"(u) : "f"(x));
    return __uint_as_float(u);
}

__device__ __forceinline__ void mma_tf32(float* d,
                                         unsigned a0, unsigned a1, unsigned a2, unsigned a3,
                                         unsigned b0, unsigned b1) {
    asm volatile(
        "mma.sync.aligned.m16n8k8.row.col.f32.tf32.tf32.f32 "
        "{%0,%1,%2,%3}, {%4,%5,%6,%7}, {%8,%9}, {%0,%1,%2,%3};\n"
        : "+f"(d[0]), "+f"(d[1]), "+f"(d[2]), "+f"(d[3])
        : "r"(a0), "r"(a1), "r"(a2), "r"(a3), "r"(b0), "r"(b1));
}

// ---------------------------------------------------------------------------
// Kernel 1: QKV projection, 3xTF32 tensor-core GEMM.
// Block tile: 128 M x 128 N, K chunks of 32. 256 threads = 8 warps, warp = m16 x n128.
// grid = (MROWS/128, 3); blockIdx.y selects (q,k,v).
// smem (floats): xh[128*36] xl[128*36] wh[128*36](transposed [n][k]) wl[128*36]
// ---------------------------------------------------------------------------
#define PROJ_SMEM_FL (4*128*36)
#define PROJ_SMEM_BYTES (PROJ_SMEM_FL*4)

__global__ __launch_bounds__(256) void qkv_proj_mma(
    const float* __restrict__ x,
    const float* __restrict__ Wk,
    const float* __restrict__ Wq,
    const float* __restrict__ Wv)
{
    extern __shared__ float sm[];
    float* xh = sm;
    float* xl = sm + 4608;
    float* wh = sm + 9216;
    float* wl = sm + 13824;

    const int t    = threadIdx.x;
    const int w    = t >> 5;
    const int lane = t & 31;
    const int g    = lane >> 2;
    const int tg   = lane & 3;
    const int m0   = w * 16;
    const int rowBase = blockIdx.x * 128;

    const float* W;
    float* outp;
    if (blockIdx.y == 0)      { W = Wq; outp = g_q; }
    else if (blockIdx.y == 1) { W = Wk; outp = g_k; }
    else                      { W = Wv; outp = g_v; }

    float acc[16][4];
    #pragma unroll
    for (int f = 0; f < 16; f++)
        #pragma unroll
        for (int j = 0; j < 4; j++) acc[f][j] = 0.f;

    for (int k0 = 0; k0 < EMB; k0 += 32) {
        // x tile: 128 rows x 32 k -> split hi/lo
        #pragma unroll
        for (int l = 0; l < 4; l++) {
            int idx = t + l*256;
            int r  = idx >> 3;
            int c4 = (idx & 7) * 4;
            float4 v = *(const float4*)(x + (size_t)(rowBase + r)*EMB + k0 + c4);
            float h0 = tf32r(v.x), h1 = tf32r(v.y), h2 = tf32r(v.z), h3 = tf32r(v.w);
            *(float4*)(xh + r*36 + c4) = make_float4(h0, h1, h2, h3);
            *(float4*)(xl + r*36 + c4) = make_float4(tf32r(v.x - h0), tf32r(v.y - h1),
                                                     tf32r(v.z - h2), tf32r(v.w - h3));
        }
        // W tile: 32 k x 128 n, stored transposed [n][k], split hi/lo
        #pragma unroll
        for (int l = 0; l < 4; l++) {
            int idx = t + l*256;
            int kk = idx >> 5;
            int n4 = (idx & 31) * 4;
            float4 v = *(const float4*)(W + (size_t)(k0 + kk)*HD + n4);
            float hv[4] = {tf32r(v.x), tf32r(v.y), tf32r(v.z), tf32r(v.w)};
            float fv[4] = {v.x, v.y, v.z, v.w};
            #pragma unroll
            for (int j = 0; j < 4; j++) {
                wh[(n4 + j)*36 + kk] = hv[j];
                wl[(n4 + j)*36 + kk] = tf32r(fv[j] - hv[j]);
            }
        }
        __syncthreads();

        #pragma unroll
        for (int kc = 0; kc < 4; kc++) {
            const int kb = kc * 8;
            unsigned ah0 = __float_as_uint(xh[(m0 + g)*36     + kb + tg]);
            unsigned ah1 = __float_as_uint(xh[(m0 + g + 8)*36 + kb + tg]);
            unsigned ah2 = __float_as_uint(xh[(m0 + g)*36     + kb + tg + 4]);
            unsigned ah3 = __float_as_uint(xh[(m0 + g + 8)*36 + kb + tg + 4]);
            unsigned al0 = __float_as_uint(xl[(m0 + g)*36     + kb + tg]);
            unsigned al1 = __float_as_uint(xl[(m0 + g + 8)*36 + kb + tg]);
            unsigned al2 = __float_as_uint(xl[(m0 + g)*36     + kb + tg + 4]);
            unsigned al3 = __float_as_uint(xl[(m0 + g + 8)*36 + kb + tg + 4]);
            #pragma unroll
            for (int f = 0; f < 16; f++) {
                const int n0 = f * 8;
                unsigned bh0 = __float_as_uint(wh[(n0 + g)*36 + kb + tg]);
                unsigned bh1 = __float_as_uint(wh[(n0 + g)*36 + kb + tg + 4]);
                unsigned bl0 = __float_as_uint(wl[(n0 + g)*36 + kb + tg]);
                unsigned bl1 = __float_as_uint(wl[(n0 + g)*36 + kb + tg + 4]);
                mma_tf32(acc[f], al0, al1, al2, al3, bh0, bh1);  // lo*hi
                mma_tf32(acc[f], ah0, ah1, ah2, ah3, bl0, bl1);  // hi*lo
                mma_tf32(acc[f], ah0, ah1, ah2, ah3, bh0, bh1);  // hi*hi
            }
        }
        __syncthreads();
    }

    // epilogue
    #pragma unroll
    for (int f = 0; f < 16; f++) {
        int col = f*8 + tg*2;
        size_t r0 = (size_t)(rowBase + m0 + g);
        *(float2*)(outp + r0*HD + col)       = make_float2(acc[f][0], acc[f][1]);
        *(float2*)(outp + (r0 + 8)*HD + col) = make_float2(acc[f][2], acc[f][3]);
    }
}

// ---------------------------------------------------------------------------
// Kernel 2: causal flash attention, tensor-core tf32.
// BQ=64 q-rows, BK=64 kv-rows per iter. 256 threads = 8 warps.
// Warp (wm = w>>1, wn = w&1): QK -> m16 x n32 slice, PV -> m16 x d64 slice.
// Q single tf32; K,V hi/lo split (2-product mma); P tf32-rounded.
// smem layout (floats):
//   Qs   [64][132]  @0       (8448)
//   Khi  [64][132]  @8448
//   Klo  [64][132]  @16896
//   Vthi [128][68]  @25344   (transposed: [d][s])
//   Vtlo [128][68]  @34048
//   Ps   [64][68]   @42752
//   m_s[64] @47104  l_s[64] @47168  alpha_s[64] @47232
// ---------------------------------------------------------------------------
#define ATT_SMEM_FL 47296
#define ATT_SMEM_BYTES (ATT_SMEM_FL*4)

__global__ __launch_bounds__(256) void attn_mma_kernel(float* __restrict__ out)
{
    extern __shared__ float sm[];
    float* Qs    = sm;
    float* Khi   = sm + 8448;
    float* Klo   = sm + 16896;
    float* Vthi  = sm + 25344;
    float* Vtlo  = sm + 34048;
    float* Ps    = sm + 42752;
    float* m_s   = sm + 47104;
    float* l_s   = sm + 47168;
    float* alp_s = sm + 47232;

    const int blk = blockIdx.x;
    const int b   = blk & 7;
    const int qt  = (SEQ/64 - 1) - (blk >> 3);   // heavy tiles first
    const int qbase = qt * 64;

    const int t    = threadIdx.x;
    const int w    = t >> 5;
    const int lane = t & 31;
    const int g    = lane >> 2;
    const int tg   = lane & 3;
    const int wm   = w >> 1;
    const int wn   = w & 1;
    const int m0   = wm * 16;

    const float* Qg = g_q + ((size_t)b*SEQ)*HD;
    const float* Kg = g_k + ((size_t)b*SEQ)*HD;
    const float* Vg = g_v + ((size_t)b*SEQ)*HD;

    // load Q tile (single tf32 round)
    #pragma unroll
    for (int l = 0; l < 8; l++) {
        int idx = t + l*256;
        int r  = idx >> 5;
        int c4 = (idx & 31) * 4;
        float4 v = *(const float4*)(Qg + (size_t)(qbase + r)*HD + c4);
        *(float4*)(Qs + r*132 + c4) =
            make_float4(tf32r(v.x), tf32r(v.y), tf32r(v.z), tf32r(v.w));
    }
    if (t < 64) { m_s[t] = -1e30f; l_s[t] = 0.f; }

    float o[8][4];
    #pragma unroll
    for (int f = 0; f < 8; f++)
        #pragma unroll
        for (int j = 0; j < 4; j++) o[f][j] = 0.f;

    const float scale = 0.08838834764831845f;  // 128^-0.5

    for (int kt = 0; kt <= qt; kt++) {
        const int kbase = kt * 64;
        __syncthreads();

        // load K (hi/lo, row-major [s][d]) and V (hi/lo, transposed [d][s])
        #pragma unroll
        for (int l = 0; l < 8; l++) {
            int idx = t + l*256;
            int r  = idx >> 5;
            int c4 = (idx & 31) * 4;
            float4 kv = *(const float4*)(Kg + (size_t)(kbase + r)*HD + c4);
            float h0 = tf32r(kv.x), h1 = tf32r(kv.y), h2 = tf32r(kv.z), h3 = tf32r(kv.w);
            *(float4*)(Khi + r*132 + c4) = make_float4(h0, h1, h2, h3);
            *(float4*)(Klo + r*132 + c4) = make_float4(tf32r(kv.x - h0), tf32r(kv.y - h1),
                                                       tf32r(kv.z - h2), tf32r(kv.w - h3));
            float4 vv = *(const float4*)(Vg + (size_t)(kbase + r)*HD + c4);
            float vh[4] = {tf32r(vv.x), tf32r(vv.y), tf32r(vv.z), tf32r(vv.w)};
            float vf[4] = {vv.x, vv.y, vv.z, vv.w};
            #pragma unroll
            for (int j = 0; j < 4; j++) {
                Vthi[(c4 + j)*68 + r] = vh[j];
                Vtlo[(c4 + j)*68 + r] = tf32r(vf[j] - vh[j]);
            }
        }
        __syncthreads();

        // S = Q @ K^T : warp computes m16 x n32 (nb = wn*32)
        float s[4][4];
        #pragma unroll
        for (int f = 0; f < 4; f++)
            #pragma unroll
            for (int j = 0; j < 4; j++) s[f][j] = 0.f;

        const int nb = wn * 32;
        #pragma unroll
        for (int kc = 0; kc < 16; kc++) {
            const int kb = kc * 8;
            unsigned a0 = __float_as_uint(Qs[(m0 + g)*132     + kb + tg]);
            unsigned a1 = __float_as_uint(Qs[(m0 + g + 8)*132 + kb + tg]);
            unsigned a2 = __float_as_uint(Qs[(m0 + g)*132     + kb + tg + 4]);
            unsigned a3 = __float_as_uint(Qs[(m0 + g + 8)*132 + kb + tg + 4]);
            #pragma unroll
            for (int f = 0; f < 4; f++) {
                const int n0 = nb + f*8;
                unsigned bh0 = __float_as_uint(Khi[(n0 + g)*132 + kb + tg]);
                unsigned bh1 = __float_as_uint(Khi[(n0 + g)*132 + kb + tg + 4]);
                unsigned bl0 = __float_as_uint(Klo[(n0 + g)*132 + kb + tg]);
                unsigned bl1 = __float_as_uint(Klo[(n0 + g)*132 + kb + tg + 4]);
                mma_tf32(s[f], a0, a1, a2, a3, bl0, bl1);
                mma_tf32(s[f], a0, a1, a2, a3, bh0, bh1);
            }
        }

        // scale + mask, store S -> Ps
        const bool diag = (kt == qt);
        #pragma unroll
        for (int f = 0; f < 4; f++) {
            int c = nb + f*8 + tg*2;
            int r0 = m0 + g, r1 = m0 + g + 8;
            float v00 = s[f][0]*scale, v01 = s[f][1]*scale;
            float v10 = s[f][2]*scale, v11 = s[f][3]*scale;
            if (diag) {
                if (c     > r0) v00 = -1e30f;
                if (c + 1 > r0) v01 = -1e30f;
                if (c     > r1) v10 = -1e30f;
                if (c + 1 > r1) v11 = -1e30f;
            }
            *(float2*)(Ps + r0*68 + c) = make_float2(v00, v01);
            *(float2*)(Ps + r1*68 + c) = make_float2(v10, v11);
        }
        __syncthreads();

        // softmax: thread -> row t>>2, 16 cols starting at (t&3)*16
        {
            int r = t >> 2;
            int q4 = t & 3;
            float vals[16];
            #pragma unroll
            for (int u = 0; u < 4; u++)
                *(float4*)(vals + u*4) = *(const float4*)(Ps + r*68 + q4*16 + u*4);
            float mx = vals[0];
            #pragma unroll
            for (int u = 1; u < 16; u++) mx = fmaxf(mx, vals[u]);
            mx = fmaxf(mx, __shfl_xor_sync(0xffffffffu, mx, 1));
            mx = fmaxf(mx, __shfl_xor_sync(0xffffffffu, mx, 2));
            float mprev = m_s[r];
            float mnew  = fmaxf(mprev, mx);
            float sumv = 0.f;
            #pragma unroll
            for (int u = 0; u < 16; u++) {
                float p = __expf(vals[u] - mnew);
                sumv += p;
                vals[u] = tf32r(p);           // round P for exact tf32 mma input
            }
            sumv += __shfl_xor_sync(0xffffffffu, sumv, 1);
            sumv += __shfl_xor_sync(0xffffffffu, sumv, 2);
            #pragma unroll
            for (int u = 0; u < 4; u++)
                *(float4*)(Ps + r*68 + q4*16 + u*4) = *(const float4*)(vals + u*4);
            if (q4 == 0) {
                float alpha = __expf(mprev - mnew);
                m_s[r]   = mnew;
                l_s[r]   = l_s[r]*alpha + sumv;
                alp_s[r] = alpha;
            }
        }
        __syncthreads();

        // rescale O by alpha, then O += P @ V  (warp: m16 x d64, db = wn*64)
        {
            float alpha0 = alp_s[m0 + g];
            float alpha1 = alp_s[m0 + g + 8];
            #pragma unroll
            for (int f = 0; f < 8; f++) {
                o[f][0] *= alpha0; o[f][1] *= alpha0;
                o[f][2] *= alpha1; o[f][3] *= alpha1;
            }
        }
        const int db = wn * 64;
        #pragma unroll
        for (int kc = 0; kc < 8; kc++) {
            const int kb = kc * 8;
            unsigned a0 = __float_as_uint(Ps[(m0 + g)*68     + kb + tg]);
            unsigned a1 = __float_as_uint(Ps[(m0 + g + 8)*68 + kb + tg]);
            unsigned a2 = __float_as_uint(Ps[(m0 + g)*68     + kb + tg + 4]);
            unsigned a3 = __float_as_uint(Ps[(m0 + g + 8)*68 + kb + tg + 4]);
            #pragma unroll
            for (int f = 0; f < 8; f++) {
                const int n0 = db + f*8;
                unsigned bh0 = __float_as_uint(Vthi[(n0 + g)*68 + kb + tg]);
                unsigned bh1 = __float_as_uint(Vthi[(n0 + g)*68 + kb + tg + 4]);
                unsigned bl0 = __float_as_uint(Vtlo[(n0 + g)*68 + kb + tg]);
                unsigned bl1 = __float_as_uint(Vtlo[(n0 + g)*68 + kb + tg + 4]);
                mma_tf32(o[f], a0, a1, a2, a3, bl0, bl1);
                mma_tf32(o[f], a0, a1, a2, a3, bh0, bh1);
            }
        }
    }

    // epilogue: normalize, write out
    __syncthreads();
    {
        float inv0 = 1.f / l_s[m0 + g];
        float inv1 = 1.f / l_s[m0 + g + 8];
        float* Ob = out + ((size_t)b*SEQ + qbase)*HD;
        const int db = wn * 64;
        #pragma unroll
        for (int f = 0; f < 8; f++) {
            int col = db + f*8 + tg*2;
            size_t r0 = (size_t)(m0 + g);
            *(float2*)(Ob + r0*HD + col) =
                make_float2(o[f][0]*inv0, o[f][1]*inv0);
            *(float2*)(Ob + (r0 + 8)*HD + col) =
                make_float2(o[f][2]*inv1, o[f][3]*inv1);
        }
    }
}

// ---------------------------------------------------------------------------
extern "C" void kernel_launch(void* const* d_in, const int* in_sizes, int n_in,
                              void* d_out, int out_size)
{
    const float* x  = (const float*)d_in[0];
    const float* Wk = (const float*)d_in[1];
    const float* Wq = (const float*)d_in[2];
    const float* Wv = (const float*)d_in[3];
    float* out = (float*)d_out;

    cudaFuncSetAttribute(qkv_proj_mma,
                         cudaFuncAttributeMaxDynamicSharedMemorySize, PROJ_SMEM_BYTES);
    cudaFuncSetAttribute(attn_mma_kernel,
                         cudaFuncAttributeMaxDynamicSharedMemorySize, ATT_SMEM_BYTES);

    dim3 g1(MROWS/128, 3);
    qkv_proj_mma<<<g1, 256, PROJ_SMEM_BYTES>>>(x, Wk, Wq, Wv);

    attn_mma_kernel<<<BATCH*(SEQ/64), 256, ATT_SMEM_BYTES>>>(out);
}

// round 5
// speedup vs baseline: 2.5417x; 2.5417x over previous
#include <cuda_runtime.h>
#include <cuda_bf16.h>
#include <math.h>

#define BATCH 8
#define SEQ   2048
#define EMB   1024
#define HD    128
#define MROWS (BATCH*SEQ)

// Scratch for projected q,k,v (fp32)
__device__ float g_q[MROWS*HD];
__device__ float g_k[MROWS*HD];
__device__ float g_v[MROWS*HD];

// ---------------------------------------------------------------------------
// bf16 helpers
// ---------------------------------------------------------------------------
__device__ __forceinline__ unsigned packbf(float x, float y) {
    __nv_bfloat162 h;
    h.x = __float2bfloat16(x); h.y = __float2bfloat16(y);
    return *reinterpret_cast<unsigned*>(&h);
}
// split (x,y) into bf16 hi pair + bf16 lo (residual) pair
__device__ __forceinline__ void split2(float x, float y, unsigned& hi, unsigned& lo) {
    __nv_bfloat16 hx = __float2bfloat16(x);
    __nv_bfloat16 hy = __float2bfloat16(y);
    float rx = x - __bfloat162float(hx);
    float ry = y - __bfloat162float(hy);
    __nv_bfloat162 hh; hh.x = hx; hh.y = hy;
    __nv_bfloat162 ll; ll.x = __float2bfloat16(rx); ll.y = __float2bfloat16(ry);
    hi = *reinterpret_cast<unsigned*>(&hh);
    lo = *reinterpret_cast<unsigned*>(&ll);
}
// convert float4 (4 consecutive k) -> hi uint2 + lo uint2, store at elem offset off2
__device__ __forceinline__ void store_split4(char* hbase, char* lbase, int off2, float4 v) {
    unsigned h0, l0, h1, l1;
    split2(v.x, v.y, h0, l0);
    split2(v.z, v.w, h1, l1);
    *(uint2*)(hbase + (size_t)off2*2) = make_uint2(h0, h1);
    *(uint2*)(lbase + (size_t)off2*2) = make_uint2(l0, l1);
}

__device__ __forceinline__ void ldsm4(unsigned* r, unsigned addr) {
    asm volatile("ldmatrix.sync.aligned.m8n8.x4.shared.b16 {%0,%1,%2,%3}, [%4];"
        : "=r"(r[0]), "=r"(r[1]), "=r"(r[2]), "=r"(r[3]) : "r"(addr));
}
__device__ __forceinline__ void ldsm4t(unsigned* r, unsigned addr) {
    asm volatile("ldmatrix.sync.aligned.m8n8.x4.trans.shared.b16 {%0,%1,%2,%3}, [%4];"
        : "=r"(r[0]), "=r"(r[1]), "=r"(r[2]), "=r"(r[3]) : "r"(addr));
}
__device__ __forceinline__ void mma_bf16(float* d, const unsigned* a, unsigned b0, unsigned b1) {
    asm volatile("mma.sync.aligned.m16n8k16.row.col.f32.bf16.bf16.f32 "
        "{%0,%1,%2,%3}, {%4,%5,%6,%7}, {%8,%9}, {%0,%1,%2,%3};"
        : "+f"(d[0]), "+f"(d[1]), "+f"(d[2]), "+f"(d[3])
        : "r"(a[0]), "r"(a[1]), "r"(a[2]), "r"(a[3]), "r"(b0), "r"(b1));
}

// ---------------------------------------------------------------------------
// Kernel 1: QKV projection, bf16 3-product (xh*wh + xh*wl + xl*wh).
// Block: 128m x 128n, k-chunks of 64. 256 threads = 8 warps (4m x 2n),
// warp tile m32 x n64. grid = (128, 3).
// smem: Xh/Xl [128][72] bf16 (k-major rows), Wh/Wl [64][136] bf16 ([k][n] rows).
// x = A (ldmatrix non-trans), W = B (ldmatrix.trans on natural [k][n] layout).
// ---------------------------------------------------------------------------
#define PJ_XH 0
#define PJ_XL 18432
#define PJ_WH 36864
#define PJ_WL 54272
#define PJ_SMEM 71680

__global__ __launch_bounds__(256) void qkv_proj_bf16(
    const float* __restrict__ x,
    const float* __restrict__ Wk,
    const float* __restrict__ Wq,
    const float* __restrict__ Wv)
{
    extern __shared__ char smraw[];
    const unsigned sb = (unsigned)__cvta_generic_to_shared(smraw);

    const int t = threadIdx.x, lane = t & 31, w = t >> 5;
    const int g = lane >> 2, tg = lane & 3;
    const int wm = w >> 1, wn = w & 1;
    const int rowBase = blockIdx.x * 128;

    const float* W;
    float* outp;
    if (blockIdx.y == 0)      { W = Wq; outp = g_q; }
    else if (blockIdx.y == 1) { W = Wk; outp = g_k; }
    else                      { W = Wv; outp = g_v; }

    float acc[2][8][4];
    #pragma unroll
    for (int mf = 0; mf < 2; mf++)
        #pragma unroll
        for (int nb = 0; nb < 8; nb++)
            #pragma unroll
            for (int j = 0; j < 4; j++) acc[mf][nb][j] = 0.f;

    for (int k0 = 0; k0 < EMB; k0 += 64) {
        // stage x: 128 rows x 64 k
        #pragma unroll
        for (int i = 0; i < 8; i++) {
            int idx = t + i*256;
            int r  = idx >> 4;
            int c4 = (idx & 15) * 4;
            float4 v = *(const float4*)(x + (size_t)(rowBase + r)*EMB + k0 + c4);
            store_split4(smraw + PJ_XH, smraw + PJ_XL, r*72 + c4, v);
        }
        // stage W: 64 k-rows x 128 n (natural layout, no transpose)
        #pragma unroll
        for (int i = 0; i < 8; i++) {
            int idx = t + i*256;
            int kk = idx >> 5;
            int n4 = (idx & 31) * 4;
            float4 v = *(const float4*)(W + (size_t)(k0 + kk)*HD + n4);
            store_split4(smraw + PJ_WH, smraw + PJ_WL, kk*136 + n4, v);
        }
        __syncthreads();

        #pragma unroll
        for (int ks = 0; ks < 4; ks++) {
            unsigned ah[2][4], al[2][4];
            #pragma unroll
            for (int mf = 0; mf < 2; mf++) {
                unsigned aoff = ((wm*32 + mf*16 + (lane & 15))*72 + ks*16 + (lane >> 4)*8)*2;
                ldsm4(ah[mf], sb + PJ_XH + aoff);
                ldsm4(al[mf], sb + PJ_XL + aoff);
            }
            unsigned bh[4][4], bl[4][4];
            #pragma unroll
            for (int nb2 = 0; nb2 < 4; nb2++) {
                int krow = ks*16 + (lane & 7) + ((lane >> 3) & 1)*8;
                int ncol = wn*64 + nb2*16 + (lane >> 4)*8;
                unsigned boff = (krow*136 + ncol)*2;
                ldsm4t(bh[nb2], sb + PJ_WH + boff);
                ldsm4t(bl[nb2], sb + PJ_WL + boff);
            }
            #pragma unroll
            for (int mf = 0; mf < 2; mf++)
                #pragma unroll
                for (int nb = 0; nb < 8; nb++) {
                    const int nb2 = nb >> 1, h = (nb & 1)*2;
                    mma_bf16(acc[mf][nb], ah[mf], bh[nb2][h], bh[nb2][h+1]);
                    mma_bf16(acc[mf][nb], ah[mf], bl[nb2][h], bl[nb2][h+1]);
                    mma_bf16(acc[mf][nb], al[mf], bh[nb2][h], bh[nb2][h+1]);
                }
        }
        __syncthreads();
    }

    // epilogue
    #pragma unroll
    for (int mf = 0; mf < 2; mf++) {
        size_t rA = (size_t)(rowBase + wm*32 + mf*16 + g);
        #pragma unroll
        for (int nb = 0; nb < 8; nb++) {
            int col = wn*64 + nb*8 + tg*2;
            *(float2*)(outp + rA*HD + col)       = make_float2(acc[mf][nb][0], acc[mf][nb][1]);
            *(float2*)(outp + (rA + 8)*HD + col) = make_float2(acc[mf][nb][2], acc[mf][nb][3]);
        }
    }
}

// ---------------------------------------------------------------------------
// Kernel 2: causal flash attention, bf16 3-product mma + ldmatrix.
// BQ = BK = 64. 256 threads = 8 warps (4m x 2n); warp: QK m16 x n32, PV m16 x d64.
// Q,K,V,P all bf16 hi/lo. V loaded with ldmatrix.trans (no staging transpose).
// Softmax on register C-frags; cross-warp (2 n-warps) max/sum via tiny smem.
// ---------------------------------------------------------------------------
#define AT_QH 0
#define AT_QL 17408
#define AT_KH 34816
#define AT_KL 52224
#define AT_VH 69632
#define AT_VL 87040
#define AT_PH 104448
#define AT_PL 113664
#define AT_MX 122880
#define AT_SX 123392
#define AT_MS 123904
#define AT_LS 124160
#define AT_SMEM 124416

__global__ __launch_bounds__(256) void attn_bf16_kernel(float* __restrict__ out)
{
    extern __shared__ char smraw[];
    const unsigned sb = (unsigned)__cvta_generic_to_shared(smraw);
    float* Mx  = (float*)(smraw + AT_MX);   // [2][64]
    float* Sx  = (float*)(smraw + AT_SX);   // [2][64]
    float* m_s = (float*)(smraw + AT_MS);   // [64]
    float* l_s = (float*)(smraw + AT_LS);   // [64]

    const int blk = blockIdx.x;
    const int b   = blk & 7;
    const int qt  = (SEQ/64 - 1) - (blk >> 3);   // heavy tiles first
    const int qbase = qt * 64;

    const int t = threadIdx.x, lane = t & 31, w = t >> 5;
    const int g = lane >> 2, tg = lane & 3;
    const int wm = w >> 1, wn = w & 1;
    const int M0 = wm * 16;

    const float* Qg = g_q + ((size_t)b*SEQ)*HD;
    const float* Kg = g_k + ((size_t)b*SEQ)*HD;
    const float* Vg = g_v + ((size_t)b*SEQ)*HD;

    // stage Q (once): 64 x 128
    #pragma unroll
    for (int i = 0; i < 8; i++) {
        int idx = t + i*256;
        int r  = idx >> 5;
        int c4 = (idx & 31) * 4;
        float4 v = *(const float4*)(Qg + (size_t)(qbase + r)*HD + c4);
        store_split4(smraw + AT_QH, smraw + AT_QL, r*136 + c4, v);
    }
    if (t < 64) { m_s[t] = -1e30f; l_s[t] = 0.f; }

    float o[8][4];
    #pragma unroll
    for (int f = 0; f < 8; f++)
        #pragma unroll
        for (int j = 0; j < 4; j++) o[f][j] = 0.f;

    const float scale = 0.08838834764831845f;  // 128^-0.5

    for (int kt = 0; kt <= qt; kt++) {
        const int kbase = kt * 64;
        __syncthreads();   // protect K/V/P from previous-iteration readers (and Q on iter 0)

        // stage K and V: 64 x 128 each
        #pragma unroll
        for (int i = 0; i < 8; i++) {
            int idx = t + i*256;
            int r  = idx >> 5;
            int c4 = (idx & 31) * 4;
            float4 kv = *(const float4*)(Kg + (size_t)(kbase + r)*HD + c4);
            store_split4(smraw + AT_KH, smraw + AT_KL, r*136 + c4, kv);
            float4 vv = *(const float4*)(Vg + (size_t)(kbase + r)*HD + c4);
            store_split4(smraw + AT_VH, smraw + AT_VL, r*136 + c4, vv);
        }
        __syncthreads();

        // ---- S = Q K^T : warp m16 x n32 ----
        float s[4][4];
        #pragma unroll
        for (int f = 0; f < 4; f++)
            #pragma unroll
            for (int j = 0; j < 4; j++) s[f][j] = 0.f;

        #pragma unroll
        for (int ks = 0; ks < 8; ks++) {
            unsigned a_h[4], a_l[4];
            {
                unsigned aoff = ((M0 + (lane & 15))*136 + ks*16 + (lane >> 4)*8)*2;
                ldsm4(a_h, sb + AT_QH + aoff);
                ldsm4(a_l, sb + AT_QL + aoff);
            }
            unsigned bh[2][4], bl[2][4];
            #pragma unroll
            for (int nb2 = 0; nb2 < 2; nb2++) {
                int nrow = wn*32 + nb2*16 + (lane & 7) + (lane >> 4)*8;
                int koff = ks*16 + ((lane >> 3) & 1)*8;
                unsigned boff = (nrow*136 + koff)*2;
                ldsm4(bh[nb2], sb + AT_KH + boff);
                ldsm4(bl[nb2], sb + AT_KL + boff);
            }
            #pragma unroll
            for (int f = 0; f < 4; f++) {
                const int nb2 = f >> 1, h = (f & 1)*2;
                mma_bf16(s[f], a_h, bh[nb2][h], bh[nb2][h+1]);
                mma_bf16(s[f], a_h, bl[nb2][h], bl[nb2][h+1]);
                mma_bf16(s[f], a_l, bh[nb2][h], bh[nb2][h+1]);
            }
        }

        // scale + causal mask
        const int rowA = qbase + M0 + g;
        const int rowB = rowA + 8;
        const bool diag = (kt == qt);
        #pragma unroll
        for (int f = 0; f < 4; f++) {
            int c = kbase + wn*32 + f*8 + tg*2;
            s[f][0] *= scale; s[f][1] *= scale; s[f][2] *= scale; s[f][3] *= scale;
            if (diag) {
                if (c     > rowA) s[f][0] = -1e30f;
                if (c + 1 > rowA) s[f][1] = -1e30f;
                if (c     > rowB) s[f][2] = -1e30f;
                if (c + 1 > rowB) s[f][3] = -1e30f;
            }
        }

        // warp-local row max (quad reduce), stash to Mx
        float mxA = fmaxf(fmaxf(s[0][0], s[0][1]), fmaxf(s[1][0], s[1][1]));
        mxA = fmaxf(mxA, fmaxf(fmaxf(s[2][0], s[2][1]), fmaxf(s[3][0], s[3][1])));
        float mxB = fmaxf(fmaxf(s[0][2], s[0][3]), fmaxf(s[1][2], s[1][3]));
        mxB = fmaxf(mxB, fmaxf(fmaxf(s[2][2], s[2][3]), fmaxf(s[3][2], s[3][3])));
        mxA = fmaxf(mxA, __shfl_xor_sync(0xffffffffu, mxA, 1));
        mxA = fmaxf(mxA, __shfl_xor_sync(0xffffffffu, mxA, 2));
        mxB = fmaxf(mxB, __shfl_xor_sync(0xffffffffu, mxB, 1));
        mxB = fmaxf(mxB, __shfl_xor_sync(0xffffffffu, mxB, 2));
        const float moldA = m_s[M0 + g];
        const float moldB = m_s[M0 + g + 8];
        if (tg == 0) {
            Mx[wn*64 + M0 + g]     = mxA;
            Mx[wn*64 + M0 + g + 8] = mxB;
        }
        __syncthreads();

        // global (both n-warps) max, alpha, p, pack P, row sums
        const float mA = fmaxf(moldA, fmaxf(Mx[M0 + g],     Mx[64 + M0 + g]));
        const float mB = fmaxf(moldB, fmaxf(Mx[M0 + g + 8], Mx[64 + M0 + g + 8]));
        const float alphaA = __expf(moldA - mA);
        const float alphaB = __expf(moldB - mB);
        if (wn == 0 && tg == 0) {
            m_s[M0 + g]     = mA;
            m_s[M0 + g + 8] = mB;
        }
        float sumA = 0.f, sumB = 0.f;
        #pragma unroll
        for (int f = 0; f < 4; f++) {
            float p0 = __expf(s[f][0] - mA);
            float p1 = __expf(s[f][1] - mA);
            float p2 = __expf(s[f][2] - mB);
            float p3 = __expf(s[f][3] - mB);
            sumA += p0 + p1; sumB += p2 + p3;
            int col = wn*32 + f*8 + tg*2;
            unsigned hi, lo;
            split2(p0, p1, hi, lo);
            *(unsigned*)(smraw + AT_PH + ((M0 + g)*72 + col)*2) = hi;
            *(unsigned*)(smraw + AT_PL + ((M0 + g)*72 + col)*2) = lo;
            split2(p2, p3, hi, lo);
            *(unsigned*)(smraw + AT_PH + ((M0 + g + 8)*72 + col)*2) = hi;
            *(unsigned*)(smraw + AT_PL + ((M0 + g + 8)*72 + col)*2) = lo;
        }
        sumA += __shfl_xor_sync(0xffffffffu, sumA, 1);
        sumA += __shfl_xor_sync(0xffffffffu, sumA, 2);
        sumB += __shfl_xor_sync(0xffffffffu, sumB, 1);
        sumB += __shfl_xor_sync(0xffffffffu, sumB, 2);
        if (tg == 0) {
            Sx[wn*64 + M0 + g]     = sumA;
            Sx[wn*64 + M0 + g + 8] = sumB;
        }
        __syncthreads();

        // l update (one lane set per row)
        if (wn == 0 && tg == 0) {
            int r = M0 + g;
            l_s[r] = l_s[r]*alphaA + Sx[r] + Sx[64 + r];
            r += 8;
            l_s[r] = l_s[r]*alphaB + Sx[r] + Sx[64 + r];
        }

        // rescale O, then O += P V  (warp: m16 x d64)
        #pragma unroll
        for (int f = 0; f < 8; f++) {
            o[f][0] *= alphaA; o[f][1] *= alphaA;
            o[f][2] *= alphaB; o[f][3] *= alphaB;
        }
        #pragma unroll
        for (int ks2 = 0; ks2 < 4; ks2++) {
            unsigned a_h[4], a_l[4];
            {
                unsigned aoff = ((M0 + (lane & 15))*72 + ks2*16 + (lane >> 4)*8)*2;
                ldsm4(a_h, sb + AT_PH + aoff);
                ldsm4(a_l, sb + AT_PL + aoff);
            }
            unsigned bh[4][4], bl[4][4];
            #pragma unroll
            for (int db2 = 0; db2 < 4; db2++) {
                int srow = ks2*16 + (lane & 7) + ((lane >> 3) & 1)*8;
                int dcol = wn*64 + db2*16 + (lane >> 4)*8;
                unsigned boff = (srow*136 + dcol)*2;
                ldsm4t(bh[db2], sb + AT_VH + boff);
                ldsm4t(bl[db2], sb + AT_VL + boff);
            }
            #pragma unroll
            for (int f = 0; f < 8; f++) {
                const int db2 = f >> 1, h = (f & 1)*2;
                mma_bf16(o[f], a_h, bh[db2][h], bh[db2][h+1]);
                mma_bf16(o[f], a_h, bl[db2][h], bl[db2][h+1]);
                mma_bf16(o[f], a_l, bh[db2][h], bh[db2][h+1]);
            }
        }
    }

    // epilogue
    __syncthreads();
    {
        const float invA = 1.f / l_s[M0 + g];
        const float invB = 1.f / l_s[M0 + g + 8];
        float* Ob = out + ((size_t)b*SEQ + qbase)*HD;
        size_t rA = (size_t)(M0 + g);
        #pragma unroll
        for (int f = 0; f < 8; f++) {
            int col = wn*64 + f*8 + tg*2;
            *(float2*)(Ob + rA*HD + col)       = make_float2(o[f][0]*invA, o[f][1]*invA);
            *(float2*)(Ob + (rA + 8)*HD + col) = make_float2(o[f][2]*invB, o[f][3]*invB);
        }
    }
}

// ---------------------------------------------------------------------------
extern "C" void kernel_launch(void* const* d_in, const int* in_sizes, int n_in,
                              void* d_out, int out_size)
{
    const float* x  = (const float*)d_in[0];
    const float* Wk = (const float*)d_in[1];
    const float* Wq = (const float*)d_in[2];
    const float* Wv = (const float*)d_in[3];
    float* out = (float*)d_out;

    cudaFuncSetAttribute(qkv_proj_bf16,
                         cudaFuncAttributeMaxDynamicSharedMemorySize, PJ_SMEM);
    cudaFuncSetAttribute(attn_bf16_kernel,
                         cudaFuncAttributeMaxDynamicSharedMemorySize, AT_SMEM);

    dim3 g1(MROWS/128, 3);
    qkv_proj_bf16<<<g1, 256, PJ_SMEM>>>(x, Wk, Wq, Wv);

    attn_bf16_kernel<<<BATCH*(SEQ/64), 256, AT_SMEM>>>(out);
}

// round 6
// speedup vs baseline: 3.0853x; 1.2139x over previous
#include <cuda_runtime.h>
#include <cuda_bf16.h>
#include <math.h>

#define BATCH 8
#define SEQ   2048
#define EMB   1024
#define HD    128
#define MROWS (BATCH*SEQ)

// Projected q,k,v as bf16 hi/lo pairs (split done once in proj epilogue)
__device__ __align__(16) __nv_bfloat16 g_qh[MROWS*HD];
__device__ __align__(16) __nv_bfloat16 g_ql[MROWS*HD];
__device__ __align__(16) __nv_bfloat16 g_kh[MROWS*HD];
__device__ __align__(16) __nv_bfloat16 g_kl[MROWS*HD];
__device__ __align__(16) __nv_bfloat16 g_vh[MROWS*HD];
__device__ __align__(16) __nv_bfloat16 g_vl[MROWS*HD];

// ---------------------------------------------------------------------------
// helpers
// ---------------------------------------------------------------------------
// split (x,y) -> packed bf16 hi pair + packed bf16 residual pair (x in low half)
__device__ __forceinline__ void split2(float x, float y, unsigned& hi, unsigned& lo) {
    asm("cvt.rn.bf16x2.f32 %0, %1, %2;" : "=r"(hi) : "f"(y), "f"(x));
    float rx = x - __uint_as_float(hi << 16);
    float ry = y - __uint_as_float(hi & 0xffff0000u);
    asm("cvt.rn.bf16x2.f32 %0, %1, %2;" : "=r"(lo) : "f"(ry), "f"(rx));
}
__device__ __forceinline__ void store_split4(char* hbase, char* lbase, int off2, float4 v) {
    unsigned h0, l0, h1, l1;
    split2(v.x, v.y, h0, l0);
    split2(v.z, v.w, h1, l1);
    *(uint2*)(hbase + (size_t)off2*2) = make_uint2(h0, h1);
    *(uint2*)(lbase + (size_t)off2*2) = make_uint2(l0, l1);
}
__device__ __forceinline__ void ldsm4(unsigned* r, unsigned addr) {
    asm volatile("ldmatrix.sync.aligned.m8n8.x4.shared.b16 {%0,%1,%2,%3}, [%4];"
        : "=r"(r[0]), "=r"(r[1]), "=r"(r[2]), "=r"(r[3]) : "r"(addr));
}
__device__ __forceinline__ void ldsm4t(unsigned* r, unsigned addr) {
    asm volatile("ldmatrix.sync.aligned.m8n8.x4.trans.shared.b16 {%0,%1,%2,%3}, [%4];"
        : "=r"(r[0]), "=r"(r[1]), "=r"(r[2]), "=r"(r[3]) : "r"(addr));
}
__device__ __forceinline__ void mma_bf16(float* d, const unsigned* a, unsigned b0, unsigned b1) {
    asm volatile("mma.sync.aligned.m16n8k16.row.col.f32.bf16.bf16.f32 "
        "{%0,%1,%2,%3}, {%4,%5,%6,%7}, {%8,%9}, {%0,%1,%2,%3};"
        : "+f"(d[0]), "+f"(d[1]), "+f"(d[2]), "+f"(d[3])
        : "r"(a[0]), "r"(a[1]), "r"(a[2]), "r"(a[3]), "r"(b0), "r"(b1));
}
__device__ __forceinline__ void cp16(unsigned dst, const void* src) {
    asm volatile("cp.async.ca.shared.global [%0], [%1], 16;" :: "r"(dst), "l"(src));
}

// ---------------------------------------------------------------------------
// Kernel 1: QKV projection, bf16 3-product, register-prefetch pipelined.
// Block 128m x 128n, k-chunks of 64, 256 threads (8 warps, 4m x 2n).
// Epilogue writes bf16 hi/lo split to global.
// ---------------------------------------------------------------------------
#define PJ_XH 0
#define PJ_XL 18432
#define PJ_WH 36864
#define PJ_WL 54272
#define PJ_SMEM 71680

__global__ __launch_bounds__(256) void qkv_proj_bf16(
    const float* __restrict__ x,
    const float* __restrict__ Wk,
    const float* __restrict__ Wq,
    const float* __restrict__ Wv)
{
    extern __shared__ char smraw[];
    const unsigned sb = (unsigned)__cvta_generic_to_shared(smraw);

    const int t = threadIdx.x, lane = t & 31, w = t >> 5;
    const int g = lane >> 2, tg = lane & 3;
    const int wm = w >> 1, wn = w & 1;
    const int rowBase = blockIdx.x * 128;

    const float* W;
    __nv_bfloat16 *oh, *ol;
    if (blockIdx.y == 0)      { W = Wq; oh = g_qh; ol = g_ql; }
    else if (blockIdx.y == 1) { W = Wk; oh = g_kh; ol = g_kl; }
    else                      { W = Wv; oh = g_vh; ol = g_vl; }

    float acc[2][8][4];
    #pragma unroll
    for (int mf = 0; mf < 2; mf++)
        #pragma unroll
        for (int nb = 0; nb < 8; nb++)
            #pragma unroll
            for (int j = 0; j < 4; j++) acc[mf][nb][j] = 0.f;

    // prefetch registers
    float4 xr[8], wr[8];
    #pragma unroll
    for (int i = 0; i < 8; i++) {
        int idx = t + i*256;
        int r = idx >> 4, c4 = (idx & 15)*4;
        xr[i] = *(const float4*)(x + (size_t)(rowBase + r)*EMB + c4);
        int kk = idx >> 5, n4 = (idx & 31)*4;
        wr[i] = *(const float4*)(W + (size_t)kk*HD + n4);
    }

    for (int kc = 0; kc < 16; kc++) {
        // store prefetched chunk (split) into smem
        #pragma unroll
        for (int i = 0; i < 8; i++) {
            int idx = t + i*256;
            int r = idx >> 4, c4 = (idx & 15)*4;
            store_split4(smraw + PJ_XH, smraw + PJ_XL, r*72 + c4, xr[i]);
            int kk = idx >> 5, n4 = (idx & 31)*4;
            store_split4(smraw + PJ_WH, smraw + PJ_WL, kk*136 + n4, wr[i]);
        }
        __syncthreads();

        // issue next chunk's global loads (in flight during mma)
        if (kc < 15) {
            const int k0 = (kc + 1)*64;
            #pragma unroll
            for (int i = 0; i < 8; i++) {
                int idx = t + i*256;
                int r = idx >> 4, c4 = (idx & 15)*4;
                xr[i] = *(const float4*)(x + (size_t)(rowBase + r)*EMB + k0 + c4);
                int kk = idx >> 5, n4 = (idx & 31)*4;
                wr[i] = *(const float4*)(W + (size_t)(k0 + kk)*HD + n4);
            }
        }

        #pragma unroll
        for (int ks = 0; ks < 4; ks++) {
            unsigned ah[2][4], al[2][4];
            #pragma unroll
            for (int mf = 0; mf < 2; mf++) {
                unsigned aoff = ((wm*32 + mf*16 + (lane & 15))*72 + ks*16 + (lane >> 4)*8)*2;
                ldsm4(ah[mf], sb + PJ_XH + aoff);
                ldsm4(al[mf], sb + PJ_XL + aoff);
            }
            unsigned bh[4][4], bl[4][4];
            #pragma unroll
            for (int nb2 = 0; nb2 < 4; nb2++) {
                int krow = ks*16 + (lane & 7) + ((lane >> 3) & 1)*8;
                int ncol = wn*64 + nb2*16 + (lane >> 4)*8;
                unsigned boff = (krow*136 + ncol)*2;
                ldsm4t(bh[nb2], sb + PJ_WH + boff);
                ldsm4t(bl[nb2], sb + PJ_WL + boff);
            }
            #pragma unroll
            for (int mf = 0; mf < 2; mf++)
                #pragma unroll
                for (int nb = 0; nb < 8; nb++) {
                    const int nb2 = nb >> 1, h = (nb & 1)*2;
                    mma_bf16(acc[mf][nb], ah[mf], bh[nb2][h], bh[nb2][h+1]);
                    mma_bf16(acc[mf][nb], ah[mf], bl[nb2][h], bl[nb2][h+1]);
                    mma_bf16(acc[mf][nb], al[mf], bh[nb2][h], bh[nb2][h+1]);
                }
        }
        __syncthreads();
    }

    // epilogue: split fp32 acc -> bf16 hi/lo global
    #pragma unroll
    for (int mf = 0; mf < 2; mf++) {
        size_t rA = (size_t)(rowBase + wm*32 + mf*16 + g);
        #pragma unroll
        for (int nb = 0; nb < 8; nb++) {
            int col = wn*64 + nb*8 + tg*2;
            unsigned hi, lo;
            split2(acc[mf][nb][0], acc[mf][nb][1], hi, lo);
            *(unsigned*)(oh + rA*HD + col) = hi;
            *(unsigned*)(ol + rA*HD + col) = lo;
            split2(acc[mf][nb][2], acc[mf][nb][3], hi, lo);
            *(unsigned*)(oh + (rA + 8)*HD + col) = hi;
            *(unsigned*)(ol + (rA + 8)*HD + col) = lo;
        }
    }
}

// ---------------------------------------------------------------------------
// Kernel 2: causal flash attention, bf16 3-product mma, cp.async double-buffered.
// BQ = BK = 64, 256 threads (8 warps, 4m x 2n).
// smem layout (bytes):
//   Qh @0  Ql @17408          (64 x 136 elems, 272 B rows)
//   stage s in {0,1} @34816 + s*69632 : Kh +0, Kl +17408, Vh +34816, Vl +52224
//   Ph @174080  Pl @183296    (64 x 72 elems)
//   Mx @192512  Sx @193024  m_s @193536  l_s @193792   total 194048
// ---------------------------------------------------------------------------
#define AT_QH 0
#define AT_QL 17408
#define AT_STG 34816
#define AT_PH 174080
#define AT_PL 183296
#define AT_MX 192512
#define AT_SX 193024
#define AT_MS 193536
#define AT_LS 193792
#define AT_SMEM 194048

__device__ __forceinline__ void stage_kv(unsigned sb, int stage, int t,
                                         const __nv_bfloat16* kh0, const __nv_bfloat16* kl0,
                                         const __nv_bfloat16* vh0, const __nv_bfloat16* vl0,
                                         int kbase)
{
    const unsigned base = sb + AT_STG + stage*69632;
    #pragma unroll
    for (int i = 0; i < 4; i++) {
        int idx = t + i*256;
        int r = idx >> 4, c8 = idx & 15;
        size_t e = (size_t)(kbase + r)*HD + c8*8;
        unsigned d = base + r*272 + c8*16;
        cp16(d,         kh0 + e);
        cp16(d + 17408, kl0 + e);
        cp16(d + 34816, vh0 + e);
        cp16(d + 52224, vl0 + e);
    }
}

__global__ __launch_bounds__(256) void attn_bf16_kernel(float* __restrict__ out)
{
    extern __shared__ char smraw[];
    const unsigned sb = (unsigned)__cvta_generic_to_shared(smraw);
    float* Mx  = (float*)(smraw + AT_MX);
    float* Sx  = (float*)(smraw + AT_SX);
    float* m_s = (float*)(smraw + AT_MS);
    float* l_s = (float*)(smraw + AT_LS);

    const int blk = blockIdx.x;
    const int b   = blk & 7;
    const int qt  = (SEQ/64 - 1) - (blk >> 3);   // heavy tiles first
    const int qbase = qt * 64;

    const int t = threadIdx.x, lane = t & 31, w = t >> 5;
    const int g = lane >> 2, tg = lane & 3;
    const int wm = w >> 1, wn = w & 1;
    const int M0 = wm * 16;

    const size_t boff = (size_t)b*SEQ*HD;
    const __nv_bfloat16 *qh = g_qh + boff, *ql = g_ql + boff;
    const __nv_bfloat16 *kh = g_kh + boff, *kl = g_kl + boff;
    const __nv_bfloat16 *vh = g_vh + boff, *vl = g_vl + boff;

    // stage Q (once) + first K/V stage, one commit group
    #pragma unroll
    for (int i = 0; i < 4; i++) {
        int idx = t + i*256;
        int r = idx >> 4, c8 = idx & 15;
        size_t e = (size_t)(qbase + r)*HD + c8*8;
        cp16(sb + AT_QH + r*272 + c8*16, qh + e);
        cp16(sb + AT_QL + r*272 + c8*16, ql + e);
    }
    stage_kv(sb, 0, t, kh, kl, vh, vl, 0);
    asm volatile("cp.async.commit_group;");

    if (t < 64) { m_s[t] = -1e30f; l_s[t] = 0.f; }

    float o[8][4];
    #pragma unroll
    for (int f = 0; f < 8; f++)
        #pragma unroll
        for (int j = 0; j < 4; j++) o[f][j] = 0.f;

    const float scale = 0.08838834764831845f;  // 128^-0.5

    for (int kt = 0; kt <= qt; kt++) {
        const int kbase = kt * 64;
        const int cur = kt & 1;
        const unsigned stK = sb + AT_STG + cur*69632;
        const unsigned stV = stK + 34816;

        __syncthreads();   // all warps done reading the buffer we're about to overwrite
        if (kt < qt) {
            stage_kv(sb, cur ^ 1, t, kh, kl, vh, vl, kbase + 64);
            asm volatile("cp.async.commit_group;");
            asm volatile("cp.async.wait_group 1;");
        } else {
            asm volatile("cp.async.wait_group 0;");
        }
        __syncthreads();   // current buffer visible to all

        // ---- S = Q K^T : warp m16 x n32 ----
        float s[4][4];
        #pragma unroll
        for (int f = 0; f < 4; f++)
            #pragma unroll
            for (int j = 0; j < 4; j++) s[f][j] = 0.f;

        #pragma unroll
        for (int ks = 0; ks < 8; ks++) {
            unsigned a_h[4], a_l[4];
            {
                unsigned aoff = ((M0 + (lane & 15))*136 + ks*16 + (lane >> 4)*8)*2;
                ldsm4(a_h, sb + AT_QH + aoff);
                ldsm4(a_l, sb + AT_QL + aoff);
            }
            unsigned bh[2][4], bl[2][4];
            #pragma unroll
            for (int nb2 = 0; nb2 < 2; nb2++) {
                int nrow = wn*32 + nb2*16 + (lane & 7) + (lane >> 4)*8;
                int koff = ks*16 + ((lane >> 3) & 1)*8;
                unsigned bo = (nrow*136 + koff)*2;
                ldsm4(bh[nb2], stK + bo);
                ldsm4(bl[nb2], stK + 17408 + bo);
            }
            #pragma unroll
            for (int f = 0; f < 4; f++) {
                const int nb2 = f >> 1, h = (f & 1)*2;
                mma_bf16(s[f], a_h, bh[nb2][h], bh[nb2][h+1]);
                mma_bf16(s[f], a_h, bl[nb2][h], bl[nb2][h+1]);
                mma_bf16(s[f], a_l, bh[nb2][h], bh[nb2][h+1]);
            }
        }

        // scale + causal mask
        const int rowA = qbase + M0 + g;
        const int rowB = rowA + 8;
        const bool diag = (kt == qt);
        #pragma unroll
        for (int f = 0; f < 4; f++) {
            int c = kbase + wn*32 + f*8 + tg*2;
            s[f][0] *= scale; s[f][1] *= scale; s[f][2] *= scale; s[f][3] *= scale;
            if (diag) {
                if (c     > rowA) s[f][0] = -1e30f;
                if (c + 1 > rowA) s[f][1] = -1e30f;
                if (c     > rowB) s[f][2] = -1e30f;
                if (c + 1 > rowB) s[f][3] = -1e30f;
            }
        }

        // warp-local row max, stash
        float mxA = fmaxf(fmaxf(s[0][0], s[0][1]), fmaxf(s[1][0], s[1][1]));
        mxA = fmaxf(mxA, fmaxf(fmaxf(s[2][0], s[2][1]), fmaxf(s[3][0], s[3][1])));
        float mxB = fmaxf(fmaxf(s[0][2], s[0][3]), fmaxf(s[1][2], s[1][3]));
        mxB = fmaxf(mxB, fmaxf(fmaxf(s[2][2], s[2][3]), fmaxf(s[3][2], s[3][3])));
        mxA = fmaxf(mxA, __shfl_xor_sync(0xffffffffu, mxA, 1));
        mxA = fmaxf(mxA, __shfl_xor_sync(0xffffffffu, mxA, 2));
        mxB = fmaxf(mxB, __shfl_xor_sync(0xffffffffu, mxB, 1));
        mxB = fmaxf(mxB, __shfl_xor_sync(0xffffffffu, mxB, 2));
        const float moldA = m_s[M0 + g];
        const float moldB = m_s[M0 + g + 8];
        if (tg == 0) {
            Mx[wn*64 + M0 + g]     = mxA;
            Mx[wn*64 + M0 + g + 8] = mxB;
        }
        __syncthreads();

        const float mA = fmaxf(moldA, fmaxf(Mx[M0 + g],     Mx[64 + M0 + g]));
        const float mB = fmaxf(moldB, fmaxf(Mx[M0 + g + 8], Mx[64 + M0 + g + 8]));
        const float alphaA = __expf(moldA - mA);
        const float alphaB = __expf(moldB - mB);
        if (wn == 0 && tg == 0) {
            m_s[M0 + g]     = mA;
            m_s[M0 + g + 8] = mB;
        }
        float sumA = 0.f, sumB = 0.f;
        #pragma unroll
        for (int f = 0; f < 4; f++) {
            float p0 = __expf(s[f][0] - mA);
            float p1 = __expf(s[f][1] - mA);
            float p2 = __expf(s[f][2] - mB);
            float p3 = __expf(s[f][3] - mB);
            sumA += p0 + p1; sumB += p2 + p3;
            int col = wn*32 + f*8 + tg*2;
            unsigned hi, lo;
            split2(p0, p1, hi, lo);
            *(unsigned*)(smraw + AT_PH + ((M0 + g)*72 + col)*2) = hi;
            *(unsigned*)(smraw + AT_PL + ((M0 + g)*72 + col)*2) = lo;
            split2(p2, p3, hi, lo);
            *(unsigned*)(smraw + AT_PH + ((M0 + g + 8)*72 + col)*2) = hi;
            *(unsigned*)(smraw + AT_PL + ((M0 + g + 8)*72 + col)*2) = lo;
        }
        sumA += __shfl_xor_sync(0xffffffffu, sumA, 1);
        sumA += __shfl_xor_sync(0xffffffffu, sumA, 2);
        sumB += __shfl_xor_sync(0xffffffffu, sumB, 1);
        sumB += __shfl_xor_sync(0xffffffffu, sumB, 2);
        if (tg == 0) {
            Sx[wn*64 + M0 + g]     = sumA;
            Sx[wn*64 + M0 + g + 8] = sumB;
        }
        __syncthreads();

        if (wn == 0 && tg == 0) {
            int r = M0 + g;
            l_s[r] = l_s[r]*alphaA + Sx[r] + Sx[64 + r];
            r += 8;
            l_s[r] = l_s[r]*alphaB + Sx[r] + Sx[64 + r];
        }

        // rescale O, then O += P V  (warp: m16 x d64)
        #pragma unroll
        for (int f = 0; f < 8; f++) {
            o[f][0] *= alphaA; o[f][1] *= alphaA;
            o[f][2] *= alphaB; o[f][3] *= alphaB;
        }
        #pragma unroll
        for (int ks2 = 0; ks2 < 4; ks2++) {
            unsigned a_h[4], a_l[4];
            {
                unsigned aoff = ((M0 + (lane & 15))*72 + ks2*16 + (lane >> 4)*8)*2;
                ldsm4(a_h, sb + AT_PH + aoff);
                ldsm4(a_l, sb + AT_PL + aoff);
            }
            unsigned bh[4][4], bl[4][4];
            #pragma unroll
            for (int db2 = 0; db2 < 4; db2++) {
                int srow = ks2*16 + (lane & 7) + ((lane >> 3) & 1)*8;
                int dcol = wn*64 + db2*16 + (lane >> 4)*8;
                unsigned bo = (srow*136 + dcol)*2;
                ldsm4t(bh[db2], stV + bo);
                ldsm4t(bl[db2], stV + 17408 + bo);
            }
            #pragma unroll
            for (int f = 0; f < 8; f++) {
                const int db2 = f >> 1, h = (f & 1)*2;
                mma_bf16(o[f], a_h, bh[db2][h], bh[db2][h+1]);
                mma_bf16(o[f], a_h, bl[db2][h], bl[db2][h+1]);
                mma_bf16(o[f], a_l, bh[db2][h], bh[db2][h+1]);
            }
        }
    }

    // epilogue
    __syncthreads();
    {
        const float invA = 1.f / l_s[M0 + g];
        const float invB = 1.f / l_s[M0 + g + 8];
        float* Ob = out + ((size_t)b*SEQ + qbase)*HD;
        size_t rA = (size_t)(M0 + g);
        #pragma unroll
        for (int f = 0; f < 8; f++) {
            int col = wn*64 + f*8 + tg*2;
            *(float2*)(Ob + rA*HD + col)       = make_float2(o[f][0]*invA, o[f][1]*invA);
            *(float2*)(Ob + (rA + 8)*HD + col) = make_float2(o[f][2]*invB, o[f][3]*invB);
        }
    }
}

// ---------------------------------------------------------------------------
extern "C" void kernel_launch(void* const* d_in, const int* in_sizes, int n_in,
                              void* d_out, int out_size)
{
    const float* x  = (const float*)d_in[0];
    const float* Wk = (const float*)d_in[1];
    const float* Wq = (const float*)d_in[2];
    const float* Wv = (const float*)d_in[3];
    float* out = (float*)d_out;

    cudaFuncSetAttribute(qkv_proj_bf16,
                         cudaFuncAttributeMaxDynamicSharedMemorySize, PJ_SMEM);
    cudaFuncSetAttribute(attn_bf16_kernel,
                         cudaFuncAttributeMaxDynamicSharedMemorySize, AT_SMEM);

    dim3 g1(MROWS/128, 3);
    qkv_proj_bf16<<<g1, 256, PJ_SMEM>>>(x, Wk, Wq, Wv);

    attn_bf16_kernel<<<BATCH*(SEQ/64), 256, AT_SMEM>>>(out);
}